// round 1
// baseline (speedup 1.0000x reference)
#include <cuda_runtime.h>
#include <cstdint>

// Problem constants
#define BB 2
#define SS 2048
#define HH 1024
#define NHEAD 16
#define HD 64
#define H3 (3*HH)
#define NTOK (BB*SS)          // 4096
#define EPSF 1e-5f

// Scratch (device globals — no allocations allowed)
__device__ float g_qkv[(size_t)NTOK * H3];   // [4096, 3072]
__device__ float g_att[(size_t)NTOK * HH];   // [4096, 1024] attention output, [B,S,H]

// ---------------------------------------------------------------------------
// GEMM:  C[M,N] = A[M,K] @ B[K,N] + bias[N]
// BM=128, BN=64, BK=16, 256 threads, 8x4 microtile per thread.
// ---------------------------------------------------------------------------
#define BM 128
#define BN 64
#define BK 16

__global__ __launch_bounds__(256)
void gemm_bias_kernel(const float* __restrict__ A, const float* __restrict__ B,
                      const float* __restrict__ bias, float* __restrict__ C,
                      int M, int N, int K)
{
    __shared__ float As[BK][BM];
    __shared__ float Bs[BK][BN];

    const int tid = threadIdx.x;
    const int bm = blockIdx.y * BM;
    const int bn = blockIdx.x * BN;

    const int ty = tid >> 4;          // 0..15 -> rows ty*8 .. ty*8+7
    const int tx = tid & 15;          // 0..15 -> cols tx*4 .. tx*4+3

    // A tile load mapping: 128x16 floats, 8 per thread (two float4 along K)
    const int a_m = tid & 127;
    const int a_k = (tid >> 7) * 8;
    // B tile load mapping: 16x64 floats, 4 per thread (one float4 along N)
    const int b_k = tid >> 4;
    const int b_n = (tid & 15) * 4;

    float acc[8][4];
    #pragma unroll
    for (int i = 0; i < 8; ++i)
        #pragma unroll
        for (int j = 0; j < 4; ++j) acc[i][j] = 0.f;

    for (int k0 = 0; k0 < K; k0 += BK) {
        const float4* ap = reinterpret_cast<const float4*>(
            &A[(size_t)(bm + a_m) * K + k0 + a_k]);
        float4 av0 = ap[0];
        float4 av1 = ap[1];
        As[a_k + 0][a_m] = av0.x; As[a_k + 1][a_m] = av0.y;
        As[a_k + 2][a_m] = av0.z; As[a_k + 3][a_m] = av0.w;
        As[a_k + 4][a_m] = av1.x; As[a_k + 5][a_m] = av1.y;
        As[a_k + 6][a_m] = av1.z; As[a_k + 7][a_m] = av1.w;

        float4 bv = *reinterpret_cast<const float4*>(
            &B[(size_t)(k0 + b_k) * N + bn + b_n]);
        *reinterpret_cast<float4*>(&Bs[b_k][b_n]) = bv;

        __syncthreads();

        #pragma unroll
        for (int kk = 0; kk < BK; ++kk) {
            float af[8], bf[4];
            #pragma unroll
            for (int i = 0; i < 8; ++i) af[i] = As[kk][ty * 8 + i];
            #pragma unroll
            for (int j = 0; j < 4; ++j) bf[j] = Bs[kk][tx * 4 + j];
            #pragma unroll
            for (int i = 0; i < 8; ++i)
                #pragma unroll
                for (int j = 0; j < 4; ++j)
                    acc[i][j] = fmaf(af[i], bf[j], acc[i][j]);
        }
        __syncthreads();
    }

    float4 bv = *reinterpret_cast<const float4*>(&bias[bn + tx * 4]);
    #pragma unroll
    for (int i = 0; i < 8; ++i) {
        float4 o;
        o.x = acc[i][0] + bv.x;
        o.y = acc[i][1] + bv.y;
        o.z = acc[i][2] + bv.z;
        o.w = acc[i][3] + bv.w;
        *reinterpret_cast<float4*>(
            &C[(size_t)(bm + ty * 8 + i) * N + bn + tx * 4]) = o;
    }
}

// ---------------------------------------------------------------------------
// QK LayerNorm over head_dim=64, in place on g_qkv. One warp per (tensor,tok,head)
// row. Softmax scale (HD^-0.5 = 0.125) folded into q.
// ---------------------------------------------------------------------------
__global__ __launch_bounds__(256)
void qk_ln_kernel(float* __restrict__ qkv,
                  const float* __restrict__ qg, const float* __restrict__ qb,
                  const float* __restrict__ kg, const float* __restrict__ kb)
{
    int warp = (blockIdx.x * blockDim.x + threadIdx.x) >> 5;
    int lane = threadIdx.x & 31;
    // 2 * 4096 * 16 = 131072 rows
    int is_k = (warp >= NTOK * NHEAD) ? 1 : 0;
    int r = warp - is_k * NTOK * NHEAD;
    int tok = r >> 4;
    int hd = r & 15;

    float* base = qkv + (size_t)tok * H3 + is_k * HH + hd * HD;
    float2 v = *reinterpret_cast<float2*>(&base[lane * 2]);

    float s = v.x + v.y;
    #pragma unroll
    for (int m = 16; m; m >>= 1) s += __shfl_xor_sync(0xffffffffu, s, m);
    float mu = s * (1.f / 64.f);

    float dx = v.x - mu, dy = v.y - mu;
    float vs = dx * dx + dy * dy;
    #pragma unroll
    for (int m = 16; m; m >>= 1) vs += __shfl_xor_sync(0xffffffffu, vs, m);
    float rstd = rsqrtf(vs * (1.f / 64.f) + EPSF);

    const float* g = is_k ? kg : qg;
    const float* be = is_k ? kb : qb;
    float scale = is_k ? 1.f : 0.125f;   // HD^-0.5 folded into q

    float2 o;
    o.x = (dx * rstd * g[lane * 2 + 0] + be[lane * 2 + 0]) * scale;
    o.y = (dy * rstd * g[lane * 2 + 1] + be[lane * 2 + 1]) * scale;
    *reinterpret_cast<float2*>(&base[lane * 2]) = o;
}

// ---------------------------------------------------------------------------
// Causal attention, FA2-style. Br=Bc=64, 256 threads (16x16), 4x4 score tile
// per thread. q/k/v read strided from qkv [tok, 3H]; out in [B,S,H].
// Smem rows padded to 68 floats (kills 16-way conflict on k_sm column reads,
// keeps float4 16B alignment: 68*4=272 % 16 == 0).
// ---------------------------------------------------------------------------
#define LDP 68
#define ATT_SMEM (4 * 64 * LDP * 4)   // q,k,v,p tiles = 69632 bytes

__global__ __launch_bounds__(256)
void attn_kernel(const float* __restrict__ qkv, float* __restrict__ out)
{
    extern __shared__ float sm[];
    float* q_sm = sm;
    float* k_sm = sm + 64 * LDP;
    float* v_sm = sm + 2 * 64 * LDP;
    float* p_sm = sm + 3 * 64 * LDP;

    const int tid = threadIdx.x;
    const int ty = tid >> 4;             // rows ty*4..+3
    const int tx = tid & 15;             // cols tx*4..+3
    const int bh = blockIdx.y;
    const int b = bh >> 4;
    const int h = bh & 15;
    const int q0 = blockIdx.x * 64;
    const size_t tok0 = (size_t)b * SS;

    // Load Q tile (64 x 64) — rows are contiguous 256B in qkv
    for (int i = tid; i < 64 * 16; i += 256) {
        int r = i >> 4;
        int c = (i & 15) * 4;
        float4 v4 = *reinterpret_cast<const float4*>(
            &qkv[(tok0 + q0 + r) * H3 + h * HD + c]);
        *reinterpret_cast<float4*>(&q_sm[r * LDP + c]) = v4;
    }

    float m_prev[4], l_run[4], o[4][4];
    #pragma unroll
    for (int i = 0; i < 4; ++i) {
        m_prev[i] = -1e30f;
        l_run[i] = 0.f;
        #pragma unroll
        for (int j = 0; j < 4; ++j) o[i][j] = 0.f;
    }
    __syncthreads();

    const int ntiles = blockIdx.x + 1;   // causal: only tiles with k0c <= q0
    for (int t = 0; t < ntiles; ++t) {
        const int k0c = t * 64;
        // Load K and V tiles
        for (int i = tid; i < 64 * 16; i += 256) {
            int r = i >> 4;
            int c = (i & 15) * 4;
            size_t rowbase = (tok0 + k0c + r) * H3 + h * HD + c;
            *reinterpret_cast<float4*>(&k_sm[r * LDP + c]) =
                *reinterpret_cast<const float4*>(&qkv[rowbase + HH]);
            *reinterpret_cast<float4*>(&v_sm[r * LDP + c]) =
                *reinterpret_cast<const float4*>(&qkv[rowbase + 2 * HH]);
        }
        __syncthreads();

        // Scores s[4][4] = q . k  (scale already folded into q)
        float s[4][4];
        #pragma unroll
        for (int i = 0; i < 4; ++i)
            #pragma unroll
            for (int j = 0; j < 4; ++j) s[i][j] = 0.f;

        #pragma unroll 8
        for (int d = 0; d < 64; ++d) {
            float aq[4], bk[4];
            #pragma unroll
            for (int i = 0; i < 4; ++i) aq[i] = q_sm[(ty * 4 + i) * LDP + d];
            #pragma unroll
            for (int j = 0; j < 4; ++j) bk[j] = k_sm[(tx * 4 + j) * LDP + d];
            #pragma unroll
            for (int i = 0; i < 4; ++i)
                #pragma unroll
                for (int j = 0; j < 4; ++j)
                    s[i][j] = fmaf(aq[i], bk[j], s[i][j]);
        }

        // Causal mask (only the diagonal tile has masked entries)
        if (t == blockIdx.x) {
            #pragma unroll
            for (int i = 0; i < 4; ++i) {
                int rg = q0 + ty * 4 + i;
                #pragma unroll
                for (int j = 0; j < 4; ++j) {
                    int cg = k0c + tx * 4 + j;
                    if (cg > rg) s[i][j] = -1e30f;
                }
            }
        }

        // Online softmax per row (reduce across the 16 lanes sharing a row)
        #pragma unroll
        for (int i = 0; i < 4; ++i) {
            float rmax = s[i][0];
            #pragma unroll
            for (int j = 1; j < 4; ++j) rmax = fmaxf(rmax, s[i][j]);
            #pragma unroll
            for (int m = 8; m; m >>= 1)
                rmax = fmaxf(rmax, __shfl_xor_sync(0xffffffffu, rmax, m));

            float m_new = fmaxf(m_prev[i], rmax);
            float p[4], rsum = 0.f;
            #pragma unroll
            for (int j = 0; j < 4; ++j) {
                p[j] = __expf(s[i][j] - m_new);
                rsum += p[j];
            }
            #pragma unroll
            for (int m = 8; m; m >>= 1)
                rsum += __shfl_xor_sync(0xffffffffu, rsum, m);

            float alpha = __expf(m_prev[i] - m_new);
            l_run[i] = l_run[i] * alpha + rsum;
            m_prev[i] = m_new;
            #pragma unroll
            for (int j = 0; j < 4; ++j) {
                o[i][j] *= alpha;
                p_sm[(ty * 4 + i) * LDP + tx * 4 + j] = p[j];
            }
        }
        __syncthreads();

        // O += P @ V
        #pragma unroll 8
        for (int c = 0; c < 64; ++c) {
            float vv[4];
            #pragma unroll
            for (int j = 0; j < 4; ++j) vv[j] = v_sm[c * LDP + tx * 4 + j];
            #pragma unroll
            for (int i = 0; i < 4; ++i) {
                float pp = p_sm[(ty * 4 + i) * LDP + c];
                #pragma unroll
                for (int j = 0; j < 4; ++j)
                    o[i][j] = fmaf(pp, vv[j], o[i][j]);
            }
        }
        __syncthreads();
    }

    // Normalize and write out [B,S,H]
    #pragma unroll
    for (int i = 0; i < 4; ++i) {
        float inv_l = 1.f / l_run[i];
        int r = q0 + ty * 4 + i;
        float4 ov;
        ov.x = o[i][0] * inv_l;
        ov.y = o[i][1] * inv_l;
        ov.z = o[i][2] * inv_l;
        ov.w = o[i][3] * inv_l;
        *reinterpret_cast<float4*>(
            &out[(tok0 + r) * HH + h * HD + tx * 4]) = ov;
    }
}

// ---------------------------------------------------------------------------
extern "C" void kernel_launch(void* const* d_in, const int* in_sizes, int n_in,
                              void* d_out, int out_size)
{
    const float* hidden = (const float*)d_in[0];
    const float* W_attn = (const float*)d_in[1];
    const float* b_attn = (const float*)d_in[2];
    const float* W_proj = (const float*)d_in[3];
    const float* b_proj = (const float*)d_in[4];
    const float* q_gamma = (const float*)d_in[5];
    const float* q_beta  = (const float*)d_in[6];
    const float* k_gamma = (const float*)d_in[7];
    const float* k_beta  = (const float*)d_in[8];
    float* out = (float*)d_out;

    float* qkv; cudaGetSymbolAddress((void**)&qkv, g_qkv);
    float* att; cudaGetSymbolAddress((void**)&att, g_att);

    // 1) QKV GEMM: [4096,1024] @ [1024,3072] + bias
    gemm_bias_kernel<<<dim3(H3 / BN, NTOK / BM), 256>>>(
        hidden, W_attn, b_attn, qkv, NTOK, H3, HH);

    // 2) QK LayerNorm in place (scale folded into q)
    qk_ln_kernel<<<(2 * NTOK * NHEAD) / 8, 256>>>(
        qkv, q_gamma, q_beta, k_gamma, k_beta);

    // 3) Causal attention
    cudaFuncSetAttribute(attn_kernel,
                         cudaFuncAttributeMaxDynamicSharedMemorySize, ATT_SMEM);
    attn_kernel<<<dim3(SS / 64, BB * NHEAD), 256, ATT_SMEM>>>(qkv, att);

    // 4) Output projection: [4096,1024] @ [1024,1024] + bias
    gemm_bias_kernel<<<dim3(HH / BN, NTOK / BM), 256>>>(
        att, W_proj, b_proj, out, NTOK, HH, HH);
}

// round 2
// speedup vs baseline: 2.7405x; 2.7405x over previous
#include <cuda_runtime.h>
#include <cstdint>

// Problem constants
#define BB 2
#define SS 2048
#define HH 1024
#define NHEAD 16
#define HD 64
#define H3 (3*HH)
#define NTOK (BB*SS)          // 4096
#define EPSF 1e-5f

// Scratch (device globals — no allocations allowed)
__device__ float g_qkv[(size_t)NTOK * H3];   // [4096, 3072]
__device__ float g_att[(size_t)NTOK * HH];   // [4096, 1024]

// ---------------------------------------------------------------------------
// tf32 helpers
// ---------------------------------------------------------------------------
__device__ __forceinline__ unsigned f2tf(float f) {
    unsigned u;
    asm("cvt.rna.tf32.f32 %0, %1;" : "=r"(u) : "f"(f));
    return u;
}

__device__ __forceinline__ void mma_tf32(float* c,
    unsigned a0, unsigned a1, unsigned a2, unsigned a3,
    unsigned b0, unsigned b1)
{
    asm volatile(
        "mma.sync.aligned.m16n8k8.row.col.f32.tf32.tf32.f32 "
        "{%0,%1,%2,%3}, {%4,%5,%6,%7}, {%8,%9}, {%0,%1,%2,%3};"
        : "+f"(c[0]), "+f"(c[1]), "+f"(c[2]), "+f"(c[3])
        : "r"(a0), "r"(a1), "r"(a2), "r"(a3), "r"(b0), "r"(b1));
}

// ---------------------------------------------------------------------------
// tf32 tensor-core GEMM:  C[M,N] = A[M,K] @ B[K,N] + bias[N]
// Block tile 128x128, 256 threads (8 warps, 2x4), warp tile 64x32.
// BK=16, double-buffered smem, pitch 136 (conflict-free fragment loads).
// ---------------------------------------------------------------------------
#define GLD 136

__global__ __launch_bounds__(256, 1)
void gemm_tf32(const float* __restrict__ A, const float* __restrict__ B,
               const float* __restrict__ bias, float* __restrict__ C,
               int M, int N, int K)
{
    __shared__ unsigned smA[2][16][GLD];   // [k][m] (tf32 bits)
    __shared__ unsigned smB[2][16][GLD];   // [k][n]

    const int tid  = threadIdx.x;
    const int warp = tid >> 5;
    const int lane = tid & 31;
    const int g    = lane >> 2;      // group id 0..7
    const int tig  = lane & 3;       // thread in group
    const int wm   = (warp >> 2) * 64;
    const int wn   = (warp & 3) * 32;
    const int bm   = blockIdx.y * 128;
    const int bn   = blockIdx.x * 128;

    // global load mappings
    const int am = tid & 127;              // A row within tile
    const int ak = (tid >> 7) * 8;         // A k offset (0 or 8)
    const int bk = tid >> 5;               // B k row (0..7, +8 for second)
    const int bn4 = lane * 4;              // B col within tile

    float acc[4][4][4];
    #pragma unroll
    for (int i = 0; i < 4; ++i)
        #pragma unroll
        for (int j = 0; j < 4; ++j)
            #pragma unroll
            for (int e = 0; e < 4; ++e) acc[i][j][e] = 0.f;

    const float* aptr = &A[(size_t)(bm + am) * K + ak];
    const float* bptr = &B[(size_t)bk * N + bn + bn4];

    // initial tile load -> buffer 0
    {
        float4 a0 = *(const float4*)(aptr + 0);
        float4 a1 = *(const float4*)(aptr + 4);
        smA[0][ak+0][am] = f2tf(a0.x); smA[0][ak+1][am] = f2tf(a0.y);
        smA[0][ak+2][am] = f2tf(a0.z); smA[0][ak+3][am] = f2tf(a0.w);
        smA[0][ak+4][am] = f2tf(a1.x); smA[0][ak+5][am] = f2tf(a1.y);
        smA[0][ak+6][am] = f2tf(a1.z); smA[0][ak+7][am] = f2tf(a1.w);
        float4 b0 = *(const float4*)(bptr);
        float4 b1 = *(const float4*)(bptr + (size_t)8 * N);
        smB[0][bk  ][bn4+0] = f2tf(b0.x); smB[0][bk  ][bn4+1] = f2tf(b0.y);
        smB[0][bk  ][bn4+2] = f2tf(b0.z); smB[0][bk  ][bn4+3] = f2tf(b0.w);
        smB[0][bk+8][bn4+0] = f2tf(b1.x); smB[0][bk+8][bn4+1] = f2tf(b1.y);
        smB[0][bk+8][bn4+2] = f2tf(b1.z); smB[0][bk+8][bn4+3] = f2tf(b1.w);
    }
    __syncthreads();

    int buf = 0;
    for (int k0 = 0; k0 < K; k0 += 16) {
        const bool has_next = (k0 + 16) < K;
        float4 pa0, pa1, pb0, pb1;
        if (has_next) {
            pa0 = *(const float4*)(aptr + k0 + 16);
            pa1 = *(const float4*)(aptr + k0 + 20);
            pb0 = *(const float4*)(bptr + (size_t)(k0 + 16) * N);
            pb1 = *(const float4*)(bptr + (size_t)(k0 + 24) * N);
        }

        // compute from smem[buf]
        #pragma unroll
        for (int kk = 0; kk < 16; kk += 8) {
            unsigned af[4][4], bf[4][2];
            #pragma unroll
            for (int i = 0; i < 4; ++i) {
                int m = wm + 16 * i + g;
                af[i][0] = smA[buf][kk + tig    ][m];
                af[i][1] = smA[buf][kk + tig    ][m + 8];
                af[i][2] = smA[buf][kk + tig + 4][m];
                af[i][3] = smA[buf][kk + tig + 4][m + 8];
            }
            #pragma unroll
            for (int j = 0; j < 4; ++j) {
                int n = wn + 8 * j + g;
                bf[j][0] = smB[buf][kk + tig    ][n];
                bf[j][1] = smB[buf][kk + tig + 4][n];
            }
            #pragma unroll
            for (int i = 0; i < 4; ++i)
                #pragma unroll
                for (int j = 0; j < 4; ++j)
                    mma_tf32(acc[i][j], af[i][0], af[i][1], af[i][2], af[i][3],
                             bf[j][0], bf[j][1]);
        }

        if (has_next) {
            int nb = buf ^ 1;
            smA[nb][ak+0][am] = f2tf(pa0.x); smA[nb][ak+1][am] = f2tf(pa0.y);
            smA[nb][ak+2][am] = f2tf(pa0.z); smA[nb][ak+3][am] = f2tf(pa0.w);
            smA[nb][ak+4][am] = f2tf(pa1.x); smA[nb][ak+5][am] = f2tf(pa1.y);
            smA[nb][ak+6][am] = f2tf(pa1.z); smA[nb][ak+7][am] = f2tf(pa1.w);
            smB[nb][bk  ][bn4+0] = f2tf(pb0.x); smB[nb][bk  ][bn4+1] = f2tf(pb0.y);
            smB[nb][bk  ][bn4+2] = f2tf(pb0.z); smB[nb][bk  ][bn4+3] = f2tf(pb0.w);
            smB[nb][bk+8][bn4+0] = f2tf(pb1.x); smB[nb][bk+8][bn4+1] = f2tf(pb1.y);
            smB[nb][bk+8][bn4+2] = f2tf(pb1.z); smB[nb][bk+8][bn4+3] = f2tf(pb1.w);
            __syncthreads();
            buf = nb;
        }
    }

    // epilogue: bias + write
    #pragma unroll
    for (int i = 0; i < 4; ++i) {
        #pragma unroll
        for (int j = 0; j < 4; ++j) {
            int gm = bm + wm + 16 * i + g;
            int gn = bn + wn + 8 * j + 2 * tig;
            float bx = bias[gn], by = bias[gn + 1];
            float2 r0 = make_float2(acc[i][j][0] + bx, acc[i][j][1] + by);
            float2 r1 = make_float2(acc[i][j][2] + bx, acc[i][j][3] + by);
            *(float2*)&C[(size_t)gm * N + gn] = r0;
            *(float2*)&C[(size_t)(gm + 8) * N + gn] = r1;
        }
    }
}

// ---------------------------------------------------------------------------
// QK LayerNorm over head_dim=64, in place. One warp per (tensor,tok,head) row.
// Softmax scale (HD^-0.5 = 0.125) folded into q.
// ---------------------------------------------------------------------------
__global__ __launch_bounds__(256)
void qk_ln_kernel(float* __restrict__ qkv,
                  const float* __restrict__ qg, const float* __restrict__ qb,
                  const float* __restrict__ kg, const float* __restrict__ kb)
{
    int warp = (blockIdx.x * blockDim.x + threadIdx.x) >> 5;
    int lane = threadIdx.x & 31;
    int is_k = (warp >= NTOK * NHEAD) ? 1 : 0;
    int r = warp - is_k * NTOK * NHEAD;
    int tok = r >> 4;
    int hd = r & 15;

    float* base = qkv + (size_t)tok * H3 + is_k * HH + hd * HD;
    float2 v = *reinterpret_cast<float2*>(&base[lane * 2]);

    float s = v.x + v.y;
    #pragma unroll
    for (int m = 16; m; m >>= 1) s += __shfl_xor_sync(0xffffffffu, s, m);
    float mu = s * (1.f / 64.f);

    float dx = v.x - mu, dy = v.y - mu;
    float vs = dx * dx + dy * dy;
    #pragma unroll
    for (int m = 16; m; m >>= 1) vs += __shfl_xor_sync(0xffffffffu, vs, m);
    float rstd = rsqrtf(vs * (1.f / 64.f) + EPSF);

    const float* gm = is_k ? kg : qg;
    const float* be = is_k ? kb : qb;
    float scale = is_k ? 1.f : 0.125f;

    float2 o;
    o.x = (dx * rstd * gm[lane * 2 + 0] + be[lane * 2 + 0]) * scale;
    o.y = (dy * rstd * gm[lane * 2 + 1] + be[lane * 2 + 1]) * scale;
    *reinterpret_cast<float2*>(&base[lane * 2]) = o;
}

// ---------------------------------------------------------------------------
// Causal attention, FA2-style with tf32 tensor MMA.
// 128 threads (4 warps); warp w owns query rows [w*16, w*16+16).
// Q/K/P smem pitch 68, V pitch 72 (conflict-free fragment loads).
// ---------------------------------------------------------------------------
#define QLD 68
#define VLD 72
#define ATT_SMEM ((3 * 64 * QLD + 64 * VLD) * 4)   // 70656 bytes

__global__ __launch_bounds__(128, 1)
void attn_tf32(const float* __restrict__ qkv, float* __restrict__ out)
{
    extern __shared__ unsigned sm[];
    unsigned* q_sm = sm;
    unsigned* k_sm = sm + 64 * QLD;
    unsigned* p_sm = sm + 2 * 64 * QLD;
    unsigned* v_sm = sm + 3 * 64 * QLD;

    const int tid  = threadIdx.x;
    const int warp = tid >> 5;
    const int lane = tid & 31;
    const int g    = lane >> 2;
    const int tig  = lane & 3;
    const int wr   = warp * 16;
    const int bh = blockIdx.y;
    const int b = bh >> 4;
    const int h = bh & 15;
    const int q0 = blockIdx.x * 64;
    const size_t tok0 = (size_t)b * SS;

    // Load Q tile (64x64) with tf32 rounding
    #pragma unroll
    for (int it = 0; it < 8; ++it) {
        int i = tid + it * 128;
        int r = i >> 4, c = (i & 15) * 4;
        float4 v4 = *(const float4*)&qkv[(tok0 + q0 + r) * H3 + h * HD + c];
        q_sm[r * QLD + c + 0] = f2tf(v4.x);
        q_sm[r * QLD + c + 1] = f2tf(v4.y);
        q_sm[r * QLD + c + 2] = f2tf(v4.z);
        q_sm[r * QLD + c + 3] = f2tf(v4.w);
    }

    float m0 = -1e30f, m1 = -1e30f, l0 = 0.f, l1 = 0.f;
    float o[8][4];
    #pragma unroll
    for (int j = 0; j < 8; ++j)
        #pragma unroll
        for (int e = 0; e < 4; ++e) o[j][e] = 0.f;
    __syncthreads();

    const int ntiles = blockIdx.x + 1;
    for (int t = 0; t < ntiles; ++t) {
        const int k0c = t * 64;
        // Load K and V tiles
        #pragma unroll
        for (int it = 0; it < 8; ++it) {
            int i = tid + it * 128;
            int r = i >> 4, c = (i & 15) * 4;
            size_t base = (tok0 + k0c + r) * H3 + h * HD + c;
            float4 kv = *(const float4*)&qkv[base + HH];
            float4 vv = *(const float4*)&qkv[base + 2 * HH];
            k_sm[r * QLD + c + 0] = f2tf(kv.x);
            k_sm[r * QLD + c + 1] = f2tf(kv.y);
            k_sm[r * QLD + c + 2] = f2tf(kv.z);
            k_sm[r * QLD + c + 3] = f2tf(kv.w);
            v_sm[r * VLD + c + 0] = f2tf(vv.x);
            v_sm[r * VLD + c + 1] = f2tf(vv.y);
            v_sm[r * VLD + c + 2] = f2tf(vv.z);
            v_sm[r * VLD + c + 3] = f2tf(vv.w);
        }
        __syncthreads();

        // S = Q @ K^T  (scale already folded into Q)
        float s[8][4];
        #pragma unroll
        for (int j = 0; j < 8; ++j)
            #pragma unroll
            for (int e = 0; e < 4; ++e) s[j][e] = 0.f;

        #pragma unroll
        for (int ks = 0; ks < 8; ++ks) {
            unsigned a0 = q_sm[(wr + g    ) * QLD + 8 * ks + tig];
            unsigned a1 = q_sm[(wr + g + 8) * QLD + 8 * ks + tig];
            unsigned a2 = q_sm[(wr + g    ) * QLD + 8 * ks + tig + 4];
            unsigned a3 = q_sm[(wr + g + 8) * QLD + 8 * ks + tig + 4];
            #pragma unroll
            for (int j = 0; j < 8; ++j) {
                unsigned b0 = k_sm[(8 * j + g) * QLD + 8 * ks + tig];
                unsigned b1 = k_sm[(8 * j + g) * QLD + 8 * ks + tig + 4];
                mma_tf32(s[j], a0, a1, a2, a3, b0, b1);
            }
        }

        // Causal mask (diagonal tile only)
        if (t == blockIdx.x) {
            int rg0 = q0 + wr + g;
            int rg1 = rg0 + 8;
            #pragma unroll
            for (int j = 0; j < 8; ++j) {
                int cg = k0c + 8 * j + 2 * tig;
                if (cg     > rg0) s[j][0] = -1e30f;
                if (cg + 1 > rg0) s[j][1] = -1e30f;
                if (cg     > rg1) s[j][2] = -1e30f;
                if (cg + 1 > rg1) s[j][3] = -1e30f;
            }
        }

        // Online softmax (rows g and g+8; reduce over quad lanes)
        float rmax0 = -1e30f, rmax1 = -1e30f;
        #pragma unroll
        for (int j = 0; j < 8; ++j) {
            rmax0 = fmaxf(rmax0, fmaxf(s[j][0], s[j][1]));
            rmax1 = fmaxf(rmax1, fmaxf(s[j][2], s[j][3]));
        }
        rmax0 = fmaxf(rmax0, __shfl_xor_sync(0xffffffffu, rmax0, 1));
        rmax0 = fmaxf(rmax0, __shfl_xor_sync(0xffffffffu, rmax0, 2));
        rmax1 = fmaxf(rmax1, __shfl_xor_sync(0xffffffffu, rmax1, 1));
        rmax1 = fmaxf(rmax1, __shfl_xor_sync(0xffffffffu, rmax1, 2));

        float mn0 = fmaxf(m0, rmax0);
        float mn1 = fmaxf(m1, rmax1);
        float sum0 = 0.f, sum1 = 0.f;
        #pragma unroll
        for (int j = 0; j < 8; ++j) {
            s[j][0] = __expf(s[j][0] - mn0); sum0 += s[j][0];
            s[j][1] = __expf(s[j][1] - mn0); sum0 += s[j][1];
            s[j][2] = __expf(s[j][2] - mn1); sum1 += s[j][2];
            s[j][3] = __expf(s[j][3] - mn1); sum1 += s[j][3];
        }
        sum0 += __shfl_xor_sync(0xffffffffu, sum0, 1);
        sum0 += __shfl_xor_sync(0xffffffffu, sum0, 2);
        sum1 += __shfl_xor_sync(0xffffffffu, sum1, 1);
        sum1 += __shfl_xor_sync(0xffffffffu, sum1, 2);

        float al0 = __expf(m0 - mn0);
        float al1 = __expf(m1 - mn1);
        l0 = l0 * al0 + sum0;
        l1 = l1 * al1 + sum1;
        m0 = mn0; m1 = mn1;

        #pragma unroll
        for (int j = 0; j < 8; ++j) {
            o[j][0] *= al0; o[j][1] *= al0;
            o[j][2] *= al1; o[j][3] *= al1;
            p_sm[(wr + g    ) * QLD + 8 * j + 2 * tig    ] = f2tf(s[j][0]);
            p_sm[(wr + g    ) * QLD + 8 * j + 2 * tig + 1] = f2tf(s[j][1]);
            p_sm[(wr + g + 8) * QLD + 8 * j + 2 * tig    ] = f2tf(s[j][2]);
            p_sm[(wr + g + 8) * QLD + 8 * j + 2 * tig + 1] = f2tf(s[j][3]);
        }
        __syncwarp();

        // O += P @ V
        #pragma unroll
        for (int ks = 0; ks < 8; ++ks) {
            unsigned a0 = p_sm[(wr + g    ) * QLD + 8 * ks + tig];
            unsigned a1 = p_sm[(wr + g + 8) * QLD + 8 * ks + tig];
            unsigned a2 = p_sm[(wr + g    ) * QLD + 8 * ks + tig + 4];
            unsigned a3 = p_sm[(wr + g + 8) * QLD + 8 * ks + tig + 4];
            #pragma unroll
            for (int j = 0; j < 8; ++j) {
                unsigned b0 = v_sm[(8 * ks + tig    ) * VLD + 8 * j + g];
                unsigned b1 = v_sm[(8 * ks + tig + 4) * VLD + 8 * j + g];
                mma_tf32(o[j], a0, a1, a2, a3, b0, b1);
            }
        }
        __syncthreads();
    }

    // Normalize and write out [B,S,H]
    float i0 = 1.f / l0, i1 = 1.f / l1;
    #pragma unroll
    for (int j = 0; j < 8; ++j) {
        int gn = h * HD + 8 * j + 2 * tig;
        float2 r0 = make_float2(o[j][0] * i0, o[j][1] * i0);
        float2 r1 = make_float2(o[j][2] * i1, o[j][3] * i1);
        *(float2*)&out[(tok0 + q0 + wr + g    ) * HH + gn] = r0;
        *(float2*)&out[(tok0 + q0 + wr + g + 8) * HH + gn] = r1;
    }
}

// ---------------------------------------------------------------------------
extern "C" void kernel_launch(void* const* d_in, const int* in_sizes, int n_in,
                              void* d_out, int out_size)
{
    const float* hidden = (const float*)d_in[0];
    const float* W_attn = (const float*)d_in[1];
    const float* b_attn = (const float*)d_in[2];
    const float* W_proj = (const float*)d_in[3];
    const float* b_proj = (const float*)d_in[4];
    const float* q_gamma = (const float*)d_in[5];
    const float* q_beta  = (const float*)d_in[6];
    const float* k_gamma = (const float*)d_in[7];
    const float* k_beta  = (const float*)d_in[8];
    float* out = (float*)d_out;

    float* qkv; cudaGetSymbolAddress((void**)&qkv, g_qkv);
    float* att; cudaGetSymbolAddress((void**)&att, g_att);

    // 1) QKV GEMM: [4096,1024] @ [1024,3072] + bias
    gemm_tf32<<<dim3(H3 / 128, NTOK / 128), 256>>>(
        hidden, W_attn, b_attn, qkv, NTOK, H3, HH);

    // 2) QK LayerNorm in place (softmax scale folded into q)
    qk_ln_kernel<<<(2 * NTOK * NHEAD) / 8, 256>>>(
        qkv, q_gamma, q_beta, k_gamma, k_beta);

    // 3) Causal attention (tf32 MMA)
    cudaFuncSetAttribute(attn_tf32,
                         cudaFuncAttributeMaxDynamicSharedMemorySize, ATT_SMEM);
    attn_tf32<<<dim3(SS / 64, BB * NHEAD), 128, ATT_SMEM>>>(qkv, att);

    // 4) Output projection: [4096,1024] @ [1024,1024] + bias
    gemm_tf32<<<dim3(HH / 128, NTOK / 128), 256>>>(
        att, W_proj, b_proj, out, NTOK, HH, HH);
}

// round 3
// speedup vs baseline: 4.0093x; 1.4630x over previous
#include <cuda_runtime.h>
#include <cstdint>

// Problem constants
#define BB 2
#define SS 2048
#define HH 1024
#define NHEAD 16
#define HD 64
#define H3 (3*HH)
#define NTOK (BB*SS)          // 4096
#define EPSF 1e-5f

// Scratch (device globals — no allocations allowed)
__device__ float g_qkv[(size_t)NTOK * H3];   // [4096, 3072]
__device__ float g_att[(size_t)NTOK * HH];   // [4096, 1024]

// ---------------------------------------------------------------------------
// tf32 helpers
// ---------------------------------------------------------------------------
__device__ __forceinline__ unsigned f2tf(float f) {
    unsigned u;
    asm("cvt.rna.tf32.f32 %0, %1;" : "=r"(u) : "f"(f));
    return u;
}

__device__ __forceinline__ void mma_tf32(float* c,
    unsigned a0, unsigned a1, unsigned a2, unsigned a3,
    unsigned b0, unsigned b1)
{
    asm volatile(
        "mma.sync.aligned.m16n8k8.row.col.f32.tf32.tf32.f32 "
        "{%0,%1,%2,%3}, {%4,%5,%6,%7}, {%8,%9}, {%0,%1,%2,%3};"
        : "+f"(c[0]), "+f"(c[1]), "+f"(c[2]), "+f"(c[3])
        : "r"(a0), "r"(a1), "r"(a2), "r"(a3), "r"(b0), "r"(b1));
}

__device__ __forceinline__ void cp16(void* smem_dst, const void* gsrc) {
    unsigned d = (unsigned)__cvta_generic_to_shared(smem_dst);
    asm volatile("cp.async.cg.shared.global [%0], [%1], 16;\n"
                 :: "r"(d), "l"(gsrc));
}
__device__ __forceinline__ void cp_commit() {
    asm volatile("cp.async.commit_group;\n");
}
__device__ __forceinline__ void cp_wait1() {
    asm volatile("cp.async.wait_group 1;\n");
}

// ---------------------------------------------------------------------------
// tf32 tensor-core GEMM:  C[M,N] = A[M,K] @ B[K,N] + bias[N]
// Block tile 128x128, 256 threads (8 warps 2x4), warp tile 64x32, BK=16.
// 3-stage cp.async pipeline; raw fp32 in smem, tf32 cvt at fragment load.
// smem: A [m][k] pitch 20 (conflict-free: bank = g*20+tig mod 32 bijective),
//       B [k][n] pitch 136 (bank = tig*8+g bijective).
// ---------------------------------------------------------------------------
#define STAGES 3

__global__ __launch_bounds__(256, 2)
void gemm_tf32(const float* __restrict__ A, const float* __restrict__ B,
               const float* __restrict__ bias, float* __restrict__ C,
               int M, int N, int K)
{
    __shared__ float sA[STAGES][128][20];
    __shared__ float sB[STAGES][16][136];

    const int tid  = threadIdx.x;
    const int warp = tid >> 5;
    const int lane = tid & 31;
    const int g    = lane >> 2;
    const int tig  = lane & 3;
    const int wm   = (warp >> 2) * 64;
    const int wn   = (warp & 3) * 32;
    const int bm   = blockIdx.y * 128;
    const int bn   = blockIdx.x * 128;

    // cp.async mappings: A tile 128x16 = 512 float4; B tile 16x128 = 512 float4
    const int a_r = tid >> 2;            // 0..63 (and +64)
    const int a_c = (tid & 3) * 4;
    const int b_r = tid >> 5;            // 0..7 (and +8)
    const int b_c = (tid & 31) * 4;

    const float* aptr0 = &A[(size_t)(bm + a_r) * K + a_c];
    const float* aptr1 = &A[(size_t)(bm + a_r + 64) * K + a_c];
    const float* bptr0 = &B[(size_t)b_r * N + bn + b_c];
    const float* bptr1 = &B[(size_t)(b_r + 8) * N + bn + b_c];

    float acc[4][4][4];
    #pragma unroll
    for (int i = 0; i < 4; ++i)
        #pragma unroll
        for (int j = 0; j < 4; ++j)
            #pragma unroll
            for (int e = 0; e < 4; ++e) acc[i][j][e] = 0.f;

    const int nkt = K >> 4;

    // prologue: stages 0..STAGES-2
    #pragma unroll
    for (int s = 0; s < STAGES - 1; ++s) {
        int k0 = s * 16;
        cp16(&sA[s][a_r][a_c],      aptr0 + k0);
        cp16(&sA[s][a_r + 64][a_c], aptr1 + k0);
        cp16(&sB[s][b_r][b_c],      bptr0 + (size_t)k0 * N);
        cp16(&sB[s][b_r + 8][b_c],  bptr1 + (size_t)k0 * N);
        cp_commit();
    }

    for (int kt = 0; kt < nkt; ++kt) {
        cp_wait1();
        __syncthreads();

        // prefetch stage kt+2
        int pf = kt + STAGES - 1;
        if (pf < nkt) {
            int s = pf % STAGES;
            int k0 = pf * 16;
            cp16(&sA[s][a_r][a_c],      aptr0 + k0);
            cp16(&sA[s][a_r + 64][a_c], aptr1 + k0);
            cp16(&sB[s][b_r][b_c],      bptr0 + (size_t)k0 * N);
            cp16(&sB[s][b_r + 8][b_c],  bptr1 + (size_t)k0 * N);
        }
        cp_commit();

        const int s = kt % STAGES;
        #pragma unroll
        for (int kk = 0; kk < 16; kk += 8) {
            unsigned af[4][4], bf[4][2];
            #pragma unroll
            for (int i = 0; i < 4; ++i) {
                int m = wm + 16 * i + g;
                af[i][0] = f2tf(sA[s][m    ][kk + tig]);
                af[i][1] = f2tf(sA[s][m + 8][kk + tig]);
                af[i][2] = f2tf(sA[s][m    ][kk + tig + 4]);
                af[i][3] = f2tf(sA[s][m + 8][kk + tig + 4]);
            }
            #pragma unroll
            for (int j = 0; j < 4; ++j) {
                int n = wn + 8 * j + g;
                bf[j][0] = f2tf(sB[s][kk + tig    ][n]);
                bf[j][1] = f2tf(sB[s][kk + tig + 4][n]);
            }
            #pragma unroll
            for (int i = 0; i < 4; ++i)
                #pragma unroll
                for (int j = 0; j < 4; ++j)
                    mma_tf32(acc[i][j], af[i][0], af[i][1], af[i][2], af[i][3],
                             bf[j][0], bf[j][1]);
        }
    }

    // epilogue: bias + write
    #pragma unroll
    for (int i = 0; i < 4; ++i) {
        #pragma unroll
        for (int j = 0; j < 4; ++j) {
            int gm = bm + wm + 16 * i + g;
            int gn = bn + wn + 8 * j + 2 * tig;
            float bx = bias[gn], by = bias[gn + 1];
            float2 r0 = make_float2(acc[i][j][0] + bx, acc[i][j][1] + by);
            float2 r1 = make_float2(acc[i][j][2] + bx, acc[i][j][3] + by);
            *(float2*)&C[(size_t)gm * N + gn] = r0;
            *(float2*)&C[(size_t)(gm + 8) * N + gn] = r1;
        }
    }
}

// ---------------------------------------------------------------------------
// QK LayerNorm over head_dim=64, in place. One warp per (tensor,tok,head) row.
// Softmax scale (HD^-0.5 = 0.125) folded into q.
// ---------------------------------------------------------------------------
__global__ __launch_bounds__(256)
void qk_ln_kernel(float* __restrict__ qkv,
                  const float* __restrict__ qg, const float* __restrict__ qb,
                  const float* __restrict__ kg, const float* __restrict__ kb)
{
    int warp = (blockIdx.x * blockDim.x + threadIdx.x) >> 5;
    int lane = threadIdx.x & 31;
    int is_k = (warp >= NTOK * NHEAD) ? 1 : 0;
    int r = warp - is_k * NTOK * NHEAD;
    int tok = r >> 4;
    int hd = r & 15;

    float* base = qkv + (size_t)tok * H3 + is_k * HH + hd * HD;
    float2 v = *reinterpret_cast<float2*>(&base[lane * 2]);

    float s = v.x + v.y;
    #pragma unroll
    for (int m = 16; m; m >>= 1) s += __shfl_xor_sync(0xffffffffu, s, m);
    float mu = s * (1.f / 64.f);

    float dx = v.x - mu, dy = v.y - mu;
    float vs = dx * dx + dy * dy;
    #pragma unroll
    for (int m = 16; m; m >>= 1) vs += __shfl_xor_sync(0xffffffffu, vs, m);
    float rstd = rsqrtf(vs * (1.f / 64.f) + EPSF);

    const float* gm = is_k ? kg : qg;
    const float* be = is_k ? kb : qb;
    float scale = is_k ? 1.f : 0.125f;

    float2 o;
    o.x = (dx * rstd * gm[lane * 2 + 0] + be[lane * 2 + 0]) * scale;
    o.y = (dy * rstd * gm[lane * 2 + 1] + be[lane * 2 + 1]) * scale;
    *reinterpret_cast<float2*>(&base[lane * 2]) = o;
}

// ---------------------------------------------------------------------------
// Causal attention, FA2-style with tf32 tensor MMA (unchanged from R2).
// 128 threads (4 warps); warp w owns query rows [w*16, w*16+16).
// ---------------------------------------------------------------------------
#define QLD 68
#define VLD 72
#define ATT_SMEM ((3 * 64 * QLD + 64 * VLD) * 4)   // 70656 bytes

__global__ __launch_bounds__(128, 1)
void attn_tf32(const float* __restrict__ qkv, float* __restrict__ out)
{
    extern __shared__ unsigned sm[];
    unsigned* q_sm = sm;
    unsigned* k_sm = sm + 64 * QLD;
    unsigned* p_sm = sm + 2 * 64 * QLD;
    unsigned* v_sm = sm + 3 * 64 * QLD;

    const int tid  = threadIdx.x;
    const int warp = tid >> 5;
    const int lane = tid & 31;
    const int g    = lane >> 2;
    const int tig  = lane & 3;
    const int wr   = warp * 16;
    const int bh = blockIdx.y;
    const int b = bh >> 4;
    const int h = bh & 15;
    const int q0 = blockIdx.x * 64;
    const size_t tok0 = (size_t)b * SS;

    #pragma unroll
    for (int it = 0; it < 8; ++it) {
        int i = tid + it * 128;
        int r = i >> 4, c = (i & 15) * 4;
        float4 v4 = *(const float4*)&qkv[(tok0 + q0 + r) * H3 + h * HD + c];
        q_sm[r * QLD + c + 0] = f2tf(v4.x);
        q_sm[r * QLD + c + 1] = f2tf(v4.y);
        q_sm[r * QLD + c + 2] = f2tf(v4.z);
        q_sm[r * QLD + c + 3] = f2tf(v4.w);
    }

    float m0 = -1e30f, m1 = -1e30f, l0 = 0.f, l1 = 0.f;
    float o[8][4];
    #pragma unroll
    for (int j = 0; j < 8; ++j)
        #pragma unroll
        for (int e = 0; e < 4; ++e) o[j][e] = 0.f;
    __syncthreads();

    const int ntiles = blockIdx.x + 1;
    for (int t = 0; t < ntiles; ++t) {
        const int k0c = t * 64;
        #pragma unroll
        for (int it = 0; it < 8; ++it) {
            int i = tid + it * 128;
            int r = i >> 4, c = (i & 15) * 4;
            size_t base = (tok0 + k0c + r) * H3 + h * HD + c;
            float4 kv = *(const float4*)&qkv[base + HH];
            float4 vv = *(const float4*)&qkv[base + 2 * HH];
            k_sm[r * QLD + c + 0] = f2tf(kv.x);
            k_sm[r * QLD + c + 1] = f2tf(kv.y);
            k_sm[r * QLD + c + 2] = f2tf(kv.z);
            k_sm[r * QLD + c + 3] = f2tf(kv.w);
            v_sm[r * VLD + c + 0] = f2tf(vv.x);
            v_sm[r * VLD + c + 1] = f2tf(vv.y);
            v_sm[r * VLD + c + 2] = f2tf(vv.z);
            v_sm[r * VLD + c + 3] = f2tf(vv.w);
        }
        __syncthreads();

        float s[8][4];
        #pragma unroll
        for (int j = 0; j < 8; ++j)
            #pragma unroll
            for (int e = 0; e < 4; ++e) s[j][e] = 0.f;

        #pragma unroll
        for (int ks = 0; ks < 8; ++ks) {
            unsigned a0 = q_sm[(wr + g    ) * QLD + 8 * ks + tig];
            unsigned a1 = q_sm[(wr + g + 8) * QLD + 8 * ks + tig];
            unsigned a2 = q_sm[(wr + g    ) * QLD + 8 * ks + tig + 4];
            unsigned a3 = q_sm[(wr + g + 8) * QLD + 8 * ks + tig + 4];
            #pragma unroll
            for (int j = 0; j < 8; ++j) {
                unsigned b0 = k_sm[(8 * j + g) * QLD + 8 * ks + tig];
                unsigned b1 = k_sm[(8 * j + g) * QLD + 8 * ks + tig + 4];
                mma_tf32(s[j], a0, a1, a2, a3, b0, b1);
            }
        }

        if (t == blockIdx.x) {
            int rg0 = q0 + wr + g;
            int rg1 = rg0 + 8;
            #pragma unroll
            for (int j = 0; j < 8; ++j) {
                int cg = k0c + 8 * j + 2 * tig;
                if (cg     > rg0) s[j][0] = -1e30f;
                if (cg + 1 > rg0) s[j][1] = -1e30f;
                if (cg     > rg1) s[j][2] = -1e30f;
                if (cg + 1 > rg1) s[j][3] = -1e30f;
            }
        }

        float rmax0 = -1e30f, rmax1 = -1e30f;
        #pragma unroll
        for (int j = 0; j < 8; ++j) {
            rmax0 = fmaxf(rmax0, fmaxf(s[j][0], s[j][1]));
            rmax1 = fmaxf(rmax1, fmaxf(s[j][2], s[j][3]));
        }
        rmax0 = fmaxf(rmax0, __shfl_xor_sync(0xffffffffu, rmax0, 1));
        rmax0 = fmaxf(rmax0, __shfl_xor_sync(0xffffffffu, rmax0, 2));
        rmax1 = fmaxf(rmax1, __shfl_xor_sync(0xffffffffu, rmax1, 1));
        rmax1 = fmaxf(rmax1, __shfl_xor_sync(0xffffffffu, rmax1, 2));

        float mn0 = fmaxf(m0, rmax0);
        float mn1 = fmaxf(m1, rmax1);
        float sum0 = 0.f, sum1 = 0.f;
        #pragma unroll
        for (int j = 0; j < 8; ++j) {
            s[j][0] = __expf(s[j][0] - mn0); sum0 += s[j][0];
            s[j][1] = __expf(s[j][1] - mn0); sum0 += s[j][1];
            s[j][2] = __expf(s[j][2] - mn1); sum1 += s[j][2];
            s[j][3] = __expf(s[j][3] - mn1); sum1 += s[j][3];
        }
        sum0 += __shfl_xor_sync(0xffffffffu, sum0, 1);
        sum0 += __shfl_xor_sync(0xffffffffu, sum0, 2);
        sum1 += __shfl_xor_sync(0xffffffffu, sum1, 1);
        sum1 += __shfl_xor_sync(0xffffffffu, sum1, 2);

        float al0 = __expf(m0 - mn0);
        float al1 = __expf(m1 - mn1);
        l0 = l0 * al0 + sum0;
        l1 = l1 * al1 + sum1;
        m0 = mn0; m1 = mn1;

        #pragma unroll
        for (int j = 0; j < 8; ++j) {
            o[j][0] *= al0; o[j][1] *= al0;
            o[j][2] *= al1; o[j][3] *= al1;
            p_sm[(wr + g    ) * QLD + 8 * j + 2 * tig    ] = f2tf(s[j][0]);
            p_sm[(wr + g    ) * QLD + 8 * j + 2 * tig + 1] = f2tf(s[j][1]);
            p_sm[(wr + g + 8) * QLD + 8 * j + 2 * tig    ] = f2tf(s[j][2]);
            p_sm[(wr + g + 8) * QLD + 8 * j + 2 * tig + 1] = f2tf(s[j][3]);
        }
        __syncwarp();

        #pragma unroll
        for (int ks = 0; ks < 8; ++ks) {
            unsigned a0 = p_sm[(wr + g    ) * QLD + 8 * ks + tig];
            unsigned a1 = p_sm[(wr + g + 8) * QLD + 8 * ks + tig];
            unsigned a2 = p_sm[(wr + g    ) * QLD + 8 * ks + tig + 4];
            unsigned a3 = p_sm[(wr + g + 8) * QLD + 8 * ks + tig + 4];
            #pragma unroll
            for (int j = 0; j < 8; ++j) {
                unsigned b0 = v_sm[(8 * ks + tig    ) * VLD + 8 * j + g];
                unsigned b1 = v_sm[(8 * ks + tig + 4) * VLD + 8 * j + g];
                mma_tf32(o[j], a0, a1, a2, a3, b0, b1);
            }
        }
        __syncthreads();
    }

    float i0 = 1.f / l0, i1 = 1.f / l1;
    #pragma unroll
    for (int j = 0; j < 8; ++j) {
        int gn = h * HD + 8 * j + 2 * tig;
        float2 r0 = make_float2(o[j][0] * i0, o[j][1] * i0);
        float2 r1 = make_float2(o[j][2] * i1, o[j][3] * i1);
        *(float2*)&out[(tok0 + q0 + wr + g    ) * HH + gn] = r0;
        *(float2*)&out[(tok0 + q0 + wr + g + 8) * HH + gn] = r1;
    }
}

// ---------------------------------------------------------------------------
extern "C" void kernel_launch(void* const* d_in, const int* in_sizes, int n_in,
                              void* d_out, int out_size)
{
    const float* hidden = (const float*)d_in[0];
    const float* W_attn = (const float*)d_in[1];
    const float* b_attn = (const float*)d_in[2];
    const float* W_proj = (const float*)d_in[3];
    const float* b_proj = (const float*)d_in[4];
    const float* q_gamma = (const float*)d_in[5];
    const float* q_beta  = (const float*)d_in[6];
    const float* k_gamma = (const float*)d_in[7];
    const float* k_beta  = (const float*)d_in[8];
    float* out = (float*)d_out;

    float* qkv; cudaGetSymbolAddress((void**)&qkv, g_qkv);
    float* att; cudaGetSymbolAddress((void**)&att, g_att);

    // 1) QKV GEMM: [4096,1024] @ [1024,3072] + bias
    gemm_tf32<<<dim3(H3 / 128, NTOK / 128), 256>>>(
        hidden, W_attn, b_attn, qkv, NTOK, H3, HH);

    // 2) QK LayerNorm in place (softmax scale folded into q)
    qk_ln_kernel<<<(2 * NTOK * NHEAD) / 8, 256>>>(
        qkv, q_gamma, q_beta, k_gamma, k_beta);

    // 3) Causal attention (tf32 MMA)
    cudaFuncSetAttribute(attn_tf32,
                         cudaFuncAttributeMaxDynamicSharedMemorySize, ATT_SMEM);
    attn_tf32<<<dim3(SS / 64, BB * NHEAD), 128, ATT_SMEM>>>(qkv, att);

    // 4) Output projection: [4096,1024] @ [1024,1024] + bias
    gemm_tf32<<<dim3(HH / 128, NTOK / 128), 256>>>(
        att, W_proj, b_proj, out, NTOK, HH, HH);
}